// round 15
// baseline (speedup 1.0000x reference)
#include <cuda_runtime.h>
#include <cuda_bf16.h>
#include <cstdint>

#define N_NODESC 8192
#define N_EDGESC 262144
#define D_FEATC  512
#define NHIDC    32
#define LATENTC  16

// output layout (float elements)
#define ADJ_OFF  0ull
#define FEAT_OFF 67108864ull                 // 8192*8192
#define Z_OFF    71303168ull                 // + 8192*512

// ---------------- scratch (no allocations allowed) ----------------
__device__ alignas(16) float g_XW1 [N_NODESC * NHIDC];
__device__ alignas(16) float g_HE  [N_NODESC * NHIDC];
__device__ alignas(16) float g_AGG1[N_NODESC * NHIDC];
__device__ alignas(16) float g_XW2 [N_NODESC * LATENTC];
__device__ alignas(16) float g_AGG2[N_NODESC * LATENTC];
__device__ alignas(16) float g_HD  [N_NODESC * NHIDC];

// ---------------- helpers ----------------
__device__ __forceinline__ unsigned long long pack2(float lo, float hi) {
    unsigned long long r;
    asm("mov.b64 %0, {%1, %2};" : "=l"(r) : "f"(lo), "f"(hi));
    return r;
}
__device__ __forceinline__ void ffma2(unsigned long long& d, unsigned long long a, unsigned long long b) {
    asm("fma.rn.f32x2 %0, %1, %2, %0;" : "+l"(d) : "l"(a), "l"(b));
}
__device__ __forceinline__ float2 unpack2(unsigned long long v) {
    float2 r;
    asm("mov.b64 {%0, %1}, %2;" : "=f"(r.x), "=f"(r.y) : "l"(v));
    return r;
}
__device__ __forceinline__ void red_add_v4(float* p, float4 v) {
    asm volatile("red.global.add.v4.f32 [%0], {%1, %2, %3, %4};"
                 :: "l"(p), "f"(v.x), "f"(v.y), "f"(v.z), "f"(v.w) : "memory");
}
__device__ __forceinline__ float sigf(float x) {
    return __fdividef(1.0f, 1.0f + __expf(-x));
}
__device__ __forceinline__ uint32_t smem_u32(const void* p) {
    uint32_t a;
    asm("{ .reg .u64 t; cvta.to.shared.u64 t, %1; cvt.u32.u64 %0, t; }" : "=r"(a) : "l"(p));
    return a;
}
__device__ __forceinline__ void ldsm_x4(uint32_t& r0, uint32_t& r1, uint32_t& r2, uint32_t& r3,
                                        uint32_t addr) {
    asm volatile("ldmatrix.sync.aligned.m8n8.x4.shared.b16 {%0,%1,%2,%3}, [%4];"
                 : "=r"(r0), "=r"(r1), "=r"(r2), "=r"(r3) : "r"(addr));
}
__device__ __forceinline__ void mma_16816(float* c, const uint32_t* a, const uint32_t* b) {
    asm volatile(
        "mma.sync.aligned.m16n8k16.row.col.f32.bf16.bf16.f32 "
        "{%0,%1,%2,%3}, {%4,%5,%6,%7}, {%8,%9}, {%0,%1,%2,%3};"
        : "+f"(c[0]), "+f"(c[1]), "+f"(c[2]), "+f"(c[3])
        : "r"(a[0]), "r"(a[1]), "r"(a[2]), "r"(a[3]), "r"(b[0]), "r"(b[1]));
}

// ---------------- critical chain kernels ----------------

// g_XW1 = X @ Wg1  (+ zero agg buffers). 64x32 tile, 256 thr, thread 4x2, f32x2.
__global__ void __launch_bounds__(256) k_transform_x(
    const float* __restrict__ X, const float* __restrict__ Wg1)
{
    __shared__ float2 As2[32][64];
    __shared__ float  Bs [32][32];
    const int t = threadIdx.x;

    {
        const float4 z4 = make_float4(0.f, 0.f, 0.f, 0.f);
        int gi = blockIdx.x * 256 + t;
#pragma unroll
        for (int q = 0; q < 3; q++) {
            int i = gi + q * 32768;
            if (i < 65536) ((float4*)g_AGG1)[i] = z4;
            else           ((float4*)g_AGG2)[i - 65536] = z4;
        }
    }

    const int rowBase = blockIdx.x * 64;
    const int tx = t & 15, ty = t >> 4;

    unsigned long long acc[4];
#pragma unroll
    for (int i = 0; i < 4; i++) acc[i] = 0ull;

    for (int k0 = 0; k0 < D_FEATC; k0 += 32) {
#pragma unroll
        for (int i = 0; i < 2; i++) {
            int idx = t + i * 256;
            int row = idx >> 3;
            int kk  = (idx & 7) * 4;
            float4 v = *(const float4*)(X + (size_t)(rowBase + row) * D_FEATC + k0 + kk);
            As2[kk + 0][row] = make_float2(v.x, v.x);
            As2[kk + 1][row] = make_float2(v.y, v.y);
            As2[kk + 2][row] = make_float2(v.z, v.z);
            As2[kk + 3][row] = make_float2(v.w, v.w);
        }
#pragma unroll
        for (int i = 0; i < 4; i++) {
            int idx = t + i * 256;          // 0..1023
            int k = idx >> 5; int c = idx & 31;
            Bs[k][c] = Wg1[(k0 + k) * NHIDC + c];
        }
        __syncthreads();
#pragma unroll
        for (int k = 0; k < 32; k++) {
            unsigned long long b2 = *(const unsigned long long*)&Bs[k][tx * 2];
#pragma unroll
            for (int i = 0; i < 4; i++) {
                unsigned long long a2 = *(const unsigned long long*)&As2[k][ty * 4 + i];
                ffma2(acc[i], a2, b2);
            }
        }
        __syncthreads();
    }

#pragma unroll
    for (int i = 0; i < 4; i++) {
        int row = rowBase + ty * 4 + i;
        float2 v = unpack2(acc[i]);
        *(float2*)&g_XW1[row * NHIDC + tx * 2] = v;
    }
}

// side-stream: g_HE = relu(X @ We1 + be1)
__global__ void __launch_bounds__(256) k_he(
    const float* __restrict__ X, const float* __restrict__ We1,
    const float* __restrict__ be1)
{
    __shared__ float2 As2[32][64];
    __shared__ float  Bs [32][32];
    const int t = threadIdx.x;
    const int rowBase = blockIdx.x * 64;
    const int tx = t & 15, ty = t >> 4;

    unsigned long long acc[4];
#pragma unroll
    for (int i = 0; i < 4; i++) acc[i] = 0ull;

    for (int k0 = 0; k0 < D_FEATC; k0 += 32) {
#pragma unroll
        for (int i = 0; i < 2; i++) {
            int idx = t + i * 256;
            int row = idx >> 3;
            int kk  = (idx & 7) * 4;
            float4 v = *(const float4*)(X + (size_t)(rowBase + row) * D_FEATC + k0 + kk);
            As2[kk + 0][row] = make_float2(v.x, v.x);
            As2[kk + 1][row] = make_float2(v.y, v.y);
            As2[kk + 2][row] = make_float2(v.z, v.z);
            As2[kk + 3][row] = make_float2(v.w, v.w);
        }
#pragma unroll
        for (int i = 0; i < 4; i++) {
            int idx = t + i * 256;
            int k = idx >> 5; int c = idx & 31;
            Bs[k][c] = We1[(k0 + k) * NHIDC + c];
        }
        __syncthreads();
#pragma unroll
        for (int k = 0; k < 32; k++) {
            unsigned long long b2 = *(const unsigned long long*)&Bs[k][tx * 2];
#pragma unroll
            for (int i = 0; i < 4; i++) {
                unsigned long long a2 = *(const unsigned long long*)&As2[k][ty * 4 + i];
                ffma2(acc[i], a2, b2);
            }
        }
        __syncthreads();
    }

    float2 bb = *(const float2*)&be1[tx * 2];
#pragma unroll
    for (int i = 0; i < 4; i++) {
        int row = rowBase + ty * 4 + i;
        float2 v = unpack2(acc[i]);
        v.x = fmaxf(v.x + bb.x, 0.f);
        v.y = fmaxf(v.y + bb.y, 0.f);
        *(float2*)&g_HE[row * NHIDC + tx * 2] = v;
    }
}

// edge aggregation layer 1: 2 edges/thread for MLP (grid 4096)
__global__ void __launch_bounds__(256) k_agg1(
    const int* __restrict__ src, const int* __restrict__ dst, const float* __restrict__ w)
{
    int gid = blockIdx.x * 256 + threadIdx.x;
    int e0 = gid >> 3;
    int e1 = e0 + (N_EDGESC / 2);
    int c = (gid & 7) * 4;
    int s0 = __ldg(&src[e0]);
    int d0 = __ldg(&dst[e0]);
    float w0 = __ldg(&w[e0]);
    int s1 = __ldg(&src[e1]);
    int d1 = __ldg(&dst[e1]);
    float w1 = __ldg(&w[e1]);
    float4 v0 = *(const float4*)&g_XW1[s0 * NHIDC + c];
    float4 v1 = *(const float4*)&g_XW1[s1 * NHIDC + c];
    v0.x *= w0; v0.y *= w0; v0.z *= w0; v0.w *= w0;
    v1.x *= w1; v1.y *= w1; v1.z *= w1; v1.w *= w1;
    red_add_v4(&g_AGG1[d0 * NHIDC + c], v0);
    red_add_v4(&g_AGG1[d1 * NHIDC + c], v1);
}

__global__ void __launch_bounds__(256) k_layer2pre(
    const float* __restrict__ bg1, const float* __restrict__ Wg2)
{
    __shared__ float h1s[16][32];
    __shared__ float Wg2s[NHIDC * LATENTC];
    const int t = threadIdx.x;
    const int n0 = blockIdx.x * 16;
    for (int i = t; i < NHIDC * LATENTC; i += 256) Wg2s[i] = Wg2[i];
#pragma unroll
    for (int i = 0; i < 2; i++) {
        int idx = t + i * 256;
        int n = idx >> 5; int c = idx & 31;
        h1s[n][c] = fmaxf(g_AGG1[(n0 + n) * NHIDC + c] + bg1[c], 0.f);
    }
    __syncthreads();
    const int n = t >> 4, j = t & 15;
    float s = 0.f;
#pragma unroll
    for (int i = 0; i < NHIDC; i++) s += h1s[n][i] * Wg2s[i * LATENTC + j];
    g_XW2[(n0 + n) * LATENTC + j] = s;
}

// edge aggregation layer 2: 2 edges/thread (grid 2048)
__global__ void __launch_bounds__(256) k_agg2(
    const int* __restrict__ src, const int* __restrict__ dst, const float* __restrict__ w)
{
    int gid = blockIdx.x * 256 + threadIdx.x;
    int e0 = gid >> 2;
    int e1 = e0 + (N_EDGESC / 2);
    int c = (gid & 3) * 4;
    int s0 = __ldg(&src[e0]);
    int d0 = __ldg(&dst[e0]);
    float w0 = __ldg(&w[e0]);
    int s1 = __ldg(&src[e1]);
    int d1 = __ldg(&dst[e1]);
    float w1 = __ldg(&w[e1]);
    float4 v0 = *(const float4*)&g_XW2[s0 * LATENTC + c];
    float4 v1 = *(const float4*)&g_XW2[s1 * LATENTC + c];
    v0.x *= w0; v0.y *= w0; v0.z *= w0; v0.w *= w0;
    v1.x *= w1; v1.y *= w1; v1.z *= w1; v1.w *= w1;
    red_add_v4(&g_AGG2[d0 * LATENTC + c], v0);
    red_add_v4(&g_AGG2[d1 * LATENTC + c], v1);
}

// za half of z: z[n][j] = relu(agg2 + bg2), j in [0,16)
__global__ void __launch_bounds__(256) k_node_za(
    const float* __restrict__ bg2, float* __restrict__ out)
{
    int gid = blockIdx.x * 256 + threadIdx.x;   // 131072 total
    int n = gid >> 4;
    int j = gid & 15;
    float za = fmaxf(g_AGG2[n * LATENTC + j] + __ldg(&bg2[j]), 0.f);
    out[Z_OFF + (size_t)n * 32 + j] = za;
}

// side-stream: zx half of z + g_HD (from g_HE)
__global__ void __launch_bounds__(128) k_node_zx(
    const float* __restrict__ We2, const float* __restrict__ be2,
    const float* __restrict__ Wd1, const float* __restrict__ bd1,
    float* __restrict__ out)
{
    __shared__ float We2s[512], Wd1s[512], be2s[16], bd1s[32];
    const int t = threadIdx.x;
    for (int i = t; i < 512; i += 128) { We2s[i] = We2[i]; Wd1s[i] = Wd1[i]; }
    if (t < 16) be2s[t] = be2[t];
    if (t < 32) bd1s[t] = bd1[t];
    __syncthreads();

    const int n = blockIdx.x * 128 + t;
    float he[32];
#pragma unroll
    for (int i = 0; i < 8; i++) {
        float4 v = *(const float4*)&g_HE[n * NHIDC + i * 4];
        he[i * 4 + 0] = v.x; he[i * 4 + 1] = v.y; he[i * 4 + 2] = v.z; he[i * 4 + 3] = v.w;
    }
    float zx[16];
#pragma unroll
    for (int j = 0; j < 16; j++) {
        float s = be2s[j];
#pragma unroll
        for (int i = 0; i < 32; i++) s += he[i] * We2s[i * 16 + j];
        zx[j] = fmaxf(s, 0.f);
    }
    float* zo = out + Z_OFF + (size_t)n * 32;
#pragma unroll
    for (int j = 0; j < 16; j++) zo[16 + j] = zx[j];
#pragma unroll
    for (int i = 0; i < 32; i++) {
        float s = bd1s[i];
#pragma unroll
        for (int j = 0; j < 16; j++) s += zx[j] * Wd1s[j * 32 + i];
        g_HD[n * NHIDC + i] = fmaxf(s, 0.f);
    }
}

__global__ void __launch_bounds__(256) k_feat(
    const float* __restrict__ Wd2, const float* __restrict__ bd2, float* __restrict__ out)
{
    __shared__ float2 hds2[16][32];
    const int t = threadIdx.x;
    const int nb = blockIdx.x * 16;
#pragma unroll
    for (int i = 0; i < 2; i++) {
        int idx = t + i * 256;
        int n = idx >> 5; int c = idx & 31;
        float v = g_HD[(nb + n) * NHIDC + c];
        hds2[n][c] = make_float2(v, v);
    }
    __syncthreads();

    const int c  = t & 127;
    const int ng = (t >> 7) * 8;
    unsigned long long accA[8], accB[8];
#pragma unroll
    for (int nn = 0; nn < 8; nn++) { accA[nn] = 0ull; accB[nn] = 0ull; }

#pragma unroll
    for (int k = 0; k < 32; k++) {
        float4 wv = __ldg((const float4*)&Wd2[k * D_FEATC + c * 4]);
        unsigned long long w01 = pack2(wv.x, wv.y);
        unsigned long long w23 = pack2(wv.z, wv.w);
#pragma unroll
        for (int nn = 0; nn < 8; nn++) {
            unsigned long long h2 = *(const unsigned long long*)&hds2[ng + nn][k];
            ffma2(accA[nn], h2, w01);
            ffma2(accB[nn], h2, w23);
        }
    }
    float4 b = __ldg((const float4*)&bd2[c * 4]);
#pragma unroll
    for (int nn = 0; nn < 8; nn++) {
        float2 vA = unpack2(accA[nn]);
        float2 vB = unpack2(accB[nn]);
        float4 o;
        o.x = fmaxf(vA.x + b.x, 0.f);
        o.y = fmaxf(vA.y + b.y, 0.f);
        o.z = fmaxf(vB.x + b.z, 0.f);
        o.w = fmaxf(vB.y + b.w, 0.f);
        *(float4*)&out[FEAT_OFF + (size_t)(nb + ng + nn) * D_FEATC + c * 4] = o;
    }
}

// ---------------- warp-MMA adjacency (compact [Hi|Lo] smem) ----------------
#define AW 72
#define ADJ_SMEM (2 * 128 * AW * 2)      // 36864 bytes

__global__ void __launch_bounds__(256) k_adj_wm(
    const float* __restrict__ zmat, float* __restrict__ out)
{
    extern __shared__ __nv_bfloat16 sm[];
    __nv_bfloat16* Asm = sm;                 // [128][AW]
    __nv_bfloat16* Bsm = sm + 128 * AW;      // [128][AW]

    const int t = threadIdx.x;
    const int wid = t >> 5;
    const int lane = t & 31;

    const int T = 64;
    const int b = blockIdx.x;
    float disc = 129.0f * 129.0f - 8.0f * (float)b;
    int it = (int)((129.0f - sqrtf(disc)) * 0.5f);
    while (it > 0 && b < it * T - (it * (it - 1)) / 2) it--;
    while (b >= (it + 1) * T - ((it + 1) * it) / 2) it++;
    const int jt = it + (b - (it * T - (it * (it - 1)) / 2));

    for (int idx = t; idx < 2048; idx += 256) {
        int half = idx >> 10;
        int rem  = idx & 1023;
        int row  = rem >> 3;
        int q    = rem & 7;
        int tl   = half ? jt : it;
        float4 v = *(const float4*)&zmat[((size_t)tl * 128 + row) * 32 + q * 4];

        __nv_bfloat16 h0 = __float2bfloat16(v.x);
        __nv_bfloat16 h1 = __float2bfloat16(v.y);
        __nv_bfloat16 h2 = __float2bfloat16(v.z);
        __nv_bfloat16 h3 = __float2bfloat16(v.w);
        __nv_bfloat16 l0 = __float2bfloat16(v.x - __bfloat162float(h0));
        __nv_bfloat16 l1 = __float2bfloat16(v.y - __bfloat162float(h1));
        __nv_bfloat16 l2 = __float2bfloat16(v.z - __bfloat162float(h2));
        __nv_bfloat16 l3 = __float2bfloat16(v.w - __bfloat162float(h3));

        __nv_bfloat162 hp0 = __nv_bfloat162(h0, h1), hp1 = __nv_bfloat162(h2, h3);
        __nv_bfloat162 lp0 = __nv_bfloat162(l0, l1), lp1 = __nv_bfloat162(l2, l3);
        uint2 hw = make_uint2(*(uint32_t*)&hp0, *(uint32_t*)&hp1);
        uint2 lw = make_uint2(*(uint32_t*)&lp0, *(uint32_t*)&lp1);

        __nv_bfloat16* base = (half ? Bsm : Asm) + row * AW + q * 4;
        *(uint2*)(base + 0)  = hw;            // Hi @ [0,32)
        *(uint2*)(base + 32) = lw;            // Lo @ [32,64)
    }
    __syncthreads();

    const int wm = wid & 3;
    const int wn = wid >> 2;
    const int rowW = wm * 32;
    const int colW = wn * 64;

    float c[2][8][4];
#pragma unroll
    for (int mi = 0; mi < 2; mi++)
#pragma unroll
        for (int ni = 0; ni < 8; ni++)
#pragma unroll
            for (int r = 0; r < 4; r++) c[mi][ni][r] = 0.f;

    const uint32_t aBase = smem_u32(Asm);
    const uint32_t bBase = smem_u32(Bsm);
    const int la_r = lane & 15;
    const int la_c = (lane >> 4) * 8;
    const int lb_r = (lane & 7) + ((lane >> 4) * 8);
    const int lb_c = ((lane >> 3) & 1) * 8;

    const int aOffs[6] = {0, 16, 0, 16, 32, 48};
    const int bOffs[6] = {0, 16, 32, 48, 0, 16};

#pragma unroll
    for (int kc = 0; kc < 6; kc++) {
        const int ka = aOffs[kc];
        const int kb = bOffs[kc];
        uint32_t a[2][4];
#pragma unroll
        for (int mi = 0; mi < 2; mi++) {
            uint32_t addr = aBase + ((rowW + mi * 16 + la_r) * AW + ka + la_c) * 2;
            ldsm_x4(a[mi][0], a[mi][1], a[mi][2], a[mi][3], addr);
        }
        uint32_t bfr[8][2];
#pragma unroll
        for (int nb2 = 0; nb2 < 4; nb2++) {
            uint32_t addr = bBase + ((colW + nb2 * 16 + lb_r) * AW + kb + lb_c) * 2;
            uint32_t t0, t1, t2, t3;
            ldsm_x4(t0, t1, t2, t3, addr);
            bfr[nb2 * 2 + 0][0] = t0; bfr[nb2 * 2 + 0][1] = t1;
            bfr[nb2 * 2 + 1][0] = t2; bfr[nb2 * 2 + 1][1] = t3;
        }
#pragma unroll
        for (int mi = 0; mi < 2; mi++)
#pragma unroll
            for (int ni = 0; ni < 8; ni++)
                mma_16816(c[mi][ni], a[mi], bfr[ni]);
    }

    const int rThr = lane >> 2;
    const int cThr = (lane & 3) * 2;
    const size_t gi0 = (size_t)it * 128;
    const size_t gj0 = (size_t)jt * 128;

#pragma unroll
    for (int mi = 0; mi < 2; mi++) {
#pragma unroll
        for (int ni = 0; ni < 8; ni++) {
            float s0 = sigf(c[mi][ni][0]);
            float s1 = sigf(c[mi][ni][1]);
            float s2 = sigf(c[mi][ni][2]);
            float s3 = sigf(c[mi][ni][3]);
            int r0 = rowW + mi * 16 + rThr;
            int cc = colW + ni * 8 + cThr;
            *(float2*)&out[(gi0 + r0)     * (size_t)N_NODESC + gj0 + cc] = make_float2(s0, s1);
            *(float2*)&out[(gi0 + r0 + 8) * (size_t)N_NODESC + gj0 + cc] = make_float2(s2, s3);
            if (it != jt) {
                out[(gj0 + cc)     * (size_t)N_NODESC + gi0 + r0]     = s0;
                out[(gj0 + cc + 1) * (size_t)N_NODESC + gi0 + r0]     = s1;
                out[(gj0 + cc)     * (size_t)N_NODESC + gi0 + r0 + 8] = s2;
                out[(gj0 + cc + 1) * (size_t)N_NODESC + gi0 + r0 + 8] = s3;
            }
        }
    }
}

// ---------------- launch ----------------
extern "C" void kernel_launch(void* const* d_in, const int* in_sizes, int n_in,
                              void* d_out, int out_size)
{
    const float* X   = (const float*)d_in[0];
    const int*   esrc= (const int*)  d_in[1];
    const int*   edst= (const int*)  d_in[2];
    const float* ew  = (const float*)d_in[3];
    const float* Wg1 = (const float*)d_in[4];
    const float* bg1 = (const float*)d_in[5];
    const float* Wg2 = (const float*)d_in[6];
    const float* bg2 = (const float*)d_in[7];
    const float* We1 = (const float*)d_in[8];
    const float* be1 = (const float*)d_in[9];
    const float* We2 = (const float*)d_in[10];
    const float* be2 = (const float*)d_in[11];
    const float* Wd1 = (const float*)d_in[12];
    const float* bd1 = (const float*)d_in[13];
    const float* Wd2 = (const float*)d_in[14];
    const float* bd2 = (const float*)d_in[15];
    float* out = (float*)d_out;

    static int initDone = 0;
    static cudaStream_t s2;
    static cudaEvent_t evFork, evZx, evJoin;
    if (!initDone) {
        cudaFuncSetAttribute(k_adj_wm, cudaFuncAttributeMaxDynamicSharedMemorySize, ADJ_SMEM);
        cudaStreamCreateWithFlags(&s2, cudaStreamNonBlocking);
        cudaEventCreateWithFlags(&evFork, cudaEventDisableTiming);
        cudaEventCreateWithFlags(&evZx,   cudaEventDisableTiming);
        cudaEventCreateWithFlags(&evJoin, cudaEventDisableTiming);
        initDone = 1;
    }

    // fork side chain immediately (depends only on inputs)
    cudaEventRecord(evFork, 0);
    cudaStreamWaitEvent(s2, evFork, 0);
    k_he      <<<128, 256, 0, s2>>>(X, We1, be1);
    k_node_zx <<<64, 128, 0, s2>>>(We2, be2, Wd1, bd1, out);
    cudaEventRecord(evZx, s2);
    k_feat    <<<512, 256, 0, s2>>>(Wd2, bd2, out);
    cudaEventRecord(evJoin, s2);

    // critical graph chain
    k_transform_x<<<128, 256>>>(X, Wg1);
    k_agg1       <<<4096, 256>>>(esrc, edst, ew);
    k_layer2pre  <<<512, 256>>>(bg1, Wg2);
    k_agg2       <<<2048, 256>>>(esrc, edst, ew);
    k_node_za    <<<512, 256>>>(bg2, out);

    cudaStreamWaitEvent(0, evZx, 0);     // zx half of z must be written
    k_adj_wm     <<<2080, 256, ADJ_SMEM>>>(out + Z_OFF, out);

    cudaStreamWaitEvent(0, evJoin, 0);   // join feat branch
}

// round 17
// speedup vs baseline: 1.1867x; 1.1867x over previous
#include <cuda_runtime.h>
#include <cuda_bf16.h>
#include <cstdint>

#define N_NODESC 8192
#define N_EDGESC 262144
#define D_FEATC  512
#define NHIDC    32
#define LATENTC  16

// output layout (float elements)
#define ADJ_OFF  0ull
#define FEAT_OFF 67108864ull                 // 8192*8192
#define Z_OFF    71303168ull                 // + 8192*512

// ---------------- scratch (no allocations allowed) ----------------
__device__ alignas(16) float g_XW1 [N_NODESC * NHIDC];   // X @ Wg1 (atomic accum)
__device__ alignas(16) float g_HE  [N_NODESC * NHIDC];   // X @ We1 pre-bias (atomic accum)
__device__ alignas(16) float g_AGG1[N_NODESC * NHIDC];
__device__ alignas(16) float g_XW2 [N_NODESC * LATENTC];
__device__ alignas(16) float g_AGG2[N_NODESC * LATENTC];
__device__ alignas(16) float g_HD  [N_NODESC * NHIDC];

// ---------------- helpers ----------------
__device__ __forceinline__ unsigned long long pack2(float lo, float hi) {
    unsigned long long r;
    asm("mov.b64 %0, {%1, %2};" : "=l"(r) : "f"(lo), "f"(hi));
    return r;
}
__device__ __forceinline__ void ffma2(unsigned long long& d, unsigned long long a, unsigned long long b) {
    asm("fma.rn.f32x2 %0, %1, %2, %0;" : "+l"(d) : "l"(a), "l"(b));
}
__device__ __forceinline__ float2 unpack2(unsigned long long v) {
    float2 r;
    asm("mov.b64 {%0, %1}, %2;" : "=f"(r.x), "=f"(r.y) : "l"(v));
    return r;
}
__device__ __forceinline__ void red_add_v4(float* p, float4 v) {
    asm volatile("red.global.add.v4.f32 [%0], {%1, %2, %3, %4};"
                 :: "l"(p), "f"(v.x), "f"(v.y), "f"(v.z), "f"(v.w) : "memory");
}
__device__ __forceinline__ float sigf(float x) {
    return __fdividef(1.0f, 1.0f + __expf(-x));
}
__device__ __forceinline__ uint32_t smem_u32(const void* p) {
    uint32_t a;
    asm("{ .reg .u64 t; cvta.to.shared.u64 t, %1; cvt.u32.u64 %0, t; }" : "=r"(a) : "l"(p));
    return a;
}
__device__ __forceinline__ void ldsm_x4(uint32_t& r0, uint32_t& r1, uint32_t& r2, uint32_t& r3,
                                        uint32_t addr) {
    asm volatile("ldmatrix.sync.aligned.m8n8.x4.shared.b16 {%0,%1,%2,%3}, [%4];"
                 : "=r"(r0), "=r"(r1), "=r"(r2), "=r"(r3) : "r"(addr));
}
__device__ __forceinline__ void mma_16816(float* c, const uint32_t* a, const uint32_t* b) {
    asm volatile(
        "mma.sync.aligned.m16n8k16.row.col.f32.bf16.bf16.f32 "
        "{%0,%1,%2,%3}, {%4,%5,%6,%7}, {%8,%9}, {%0,%1,%2,%3};"
        : "+f"(c[0]), "+f"(c[1]), "+f"(c[2]), "+f"(c[3])
        : "r"(a[0]), "r"(a[1]), "r"(a[2]), "r"(a[3]), "r"(b[0]), "r"(b[1]));
}

// ---------------- kernels ----------------

// zero accumulation buffers: XW1, HE(pre), AGG1, AGG2 -> 229376 float4 exactly
__global__ void __launch_bounds__(256) k_zero() {
    int i = blockIdx.x * 256 + threadIdx.x;
    const float4 z = make_float4(0.f, 0.f, 0.f, 0.f);
    if (i < 65536)       ((float4*)g_XW1)[i] = z;
    else if (i < 131072) ((float4*)g_HE )[i - 65536] = z;
    else if (i < 196608) ((float4*)g_AGG1)[i - 131072] = z;
    else                 ((float4*)g_AGG2)[i - 196608] = z;
}

// fused transform, K-split x4, atomic accumulation:
//   g_XW1 += X[:, kc*128:+128] @ Wg1[kc*128:+128, :]
//   g_HE  += X[:, kc*128:+128] @ We1[kc*128:+128, :]   (bias+relu applied later)
// grid 512 = 128 row-blocks (64 rows) x 4 K-chunks. 256 thr, 4x4 tile, f32x2.
__global__ void __launch_bounds__(256) k_transform(
    const float* __restrict__ X, const float* __restrict__ Wg1,
    const float* __restrict__ We1)
{
    __shared__ float2 As2[32][64];     // duplicated (v,v) 16KB
    __shared__ float  Bs [32][64];     // 8KB
    const int t = threadIdx.x;
    const int rb = blockIdx.x >> 2;
    const int kc = blockIdx.x & 3;
    const int rowBase = rb * 64;
    const int kBase = kc * 128;
    const int tx = t & 15, ty = t >> 4;

    unsigned long long acc[4][2];
#pragma unroll
    for (int i = 0; i < 4; i++) { acc[i][0] = 0ull; acc[i][1] = 0ull; }

    for (int k0 = 0; k0 < 128; k0 += 32) {
#pragma unroll
        for (int i = 0; i < 2; i++) {
            int idx = t + i * 256;
            int row = idx >> 3;
            int kk  = (idx & 7) * 4;
            float4 v = *(const float4*)(X + (size_t)(rowBase + row) * D_FEATC + kBase + k0 + kk);
            As2[kk + 0][row] = make_float2(v.x, v.x);
            As2[kk + 1][row] = make_float2(v.y, v.y);
            As2[kk + 2][row] = make_float2(v.z, v.z);
            As2[kk + 3][row] = make_float2(v.w, v.w);
        }
#pragma unroll
        for (int i = 0; i < 8; i++) {
            int idx = t + i * 256;
            int k = idx >> 6; int c = idx & 63;
            Bs[k][c] = (c < 32) ? Wg1[(kBase + k0 + k) * NHIDC + c]
                                : We1[(kBase + k0 + k) * NHIDC + (c - 32)];
        }
        __syncthreads();
#pragma unroll
        for (int k = 0; k < 32; k++) {
            unsigned long long a2[4];
#pragma unroll
            for (int i = 0; i < 4; i++) a2[i] = *(const unsigned long long*)&As2[k][ty * 4 + i];
            unsigned long long b2a = *(const unsigned long long*)&Bs[k][tx * 4 + 0];
            unsigned long long b2b = *(const unsigned long long*)&Bs[k][tx * 4 + 2];
#pragma unroll
            for (int i = 0; i < 4; i++) { ffma2(acc[i][0], a2[i], b2a); ffma2(acc[i][1], a2[i], b2b); }
        }
        __syncthreads();
    }

    const int c0 = tx * 4;
#pragma unroll
    for (int i = 0; i < 4; i++) {
        int row = rowBase + ty * 4 + i;
        float2 v0 = unpack2(acc[i][0]);
        float2 v1 = unpack2(acc[i][1]);
        float4 o = make_float4(v0.x, v0.y, v1.x, v1.y);
        if (c0 < 32) red_add_v4(&g_XW1[row * NHIDC + c0], o);
        else         red_add_v4(&g_HE [row * NHIDC + (c0 - 32)], o);
    }
}

// edge aggregation layer 1: 2 edges/thread (grid 4096)
__global__ void __launch_bounds__(256) k_agg1(
    const int* __restrict__ src, const int* __restrict__ dst, const float* __restrict__ w)
{
    int gid = blockIdx.x * 256 + threadIdx.x;
    int e0 = gid >> 3;
    int e1 = e0 + (N_EDGESC / 2);
    int c = (gid & 7) * 4;
    int s0 = __ldg(&src[e0]);
    int d0 = __ldg(&dst[e0]);
    float w0 = __ldg(&w[e0]);
    int s1 = __ldg(&src[e1]);
    int d1 = __ldg(&dst[e1]);
    float w1 = __ldg(&w[e1]);
    float4 v0 = *(const float4*)&g_XW1[s0 * NHIDC + c];
    float4 v1 = *(const float4*)&g_XW1[s1 * NHIDC + c];
    v0.x *= w0; v0.y *= w0; v0.z *= w0; v0.w *= w0;
    v1.x *= w1; v1.y *= w1; v1.z *= w1; v1.w *= w1;
    red_add_v4(&g_AGG1[d0 * NHIDC + c], v0);
    red_add_v4(&g_AGG1[d1 * NHIDC + c], v1);
}

__global__ void __launch_bounds__(256) k_layer2pre(
    const float* __restrict__ bg1, const float* __restrict__ Wg2)
{
    __shared__ float h1s[16][32];
    __shared__ float Wg2s[NHIDC * LATENTC];
    const int t = threadIdx.x;
    const int n0 = blockIdx.x * 16;
    for (int i = t; i < NHIDC * LATENTC; i += 256) Wg2s[i] = Wg2[i];
#pragma unroll
    for (int i = 0; i < 2; i++) {
        int idx = t + i * 256;
        int n = idx >> 5; int c = idx & 31;
        h1s[n][c] = fmaxf(g_AGG1[(n0 + n) * NHIDC + c] + bg1[c], 0.f);
    }
    __syncthreads();
    const int n = t >> 4, j = t & 15;
    float s = 0.f;
#pragma unroll
    for (int i = 0; i < NHIDC; i++) s += h1s[n][i] * Wg2s[i * LATENTC + j];
    g_XW2[(n0 + n) * LATENTC + j] = s;
}

// edge aggregation layer 2: 2 edges/thread (grid 2048)
__global__ void __launch_bounds__(256) k_agg2(
    const int* __restrict__ src, const int* __restrict__ dst, const float* __restrict__ w)
{
    int gid = blockIdx.x * 256 + threadIdx.x;
    int e0 = gid >> 2;
    int e1 = e0 + (N_EDGESC / 2);
    int c = (gid & 3) * 4;
    int s0 = __ldg(&src[e0]);
    int d0 = __ldg(&dst[e0]);
    float w0 = __ldg(&w[e0]);
    int s1 = __ldg(&src[e1]);
    int d1 = __ldg(&dst[e1]);
    float w1 = __ldg(&w[e1]);
    float4 v0 = *(const float4*)&g_XW2[s0 * LATENTC + c];
    float4 v1 = *(const float4*)&g_XW2[s1 * LATENTC + c];
    v0.x *= w0; v0.y *= w0; v0.z *= w0; v0.w *= w0;
    v1.x *= w1; v1.y *= w1; v1.z *= w1; v1.w *= w1;
    red_add_v4(&g_AGG2[d0 * LATENTC + c], v0);
    red_add_v4(&g_AGG2[d1 * LATENTC + c], v1);
}

// za half of z
__global__ void __launch_bounds__(256) k_node_za(
    const float* __restrict__ bg2, float* __restrict__ out)
{
    int gid = blockIdx.x * 256 + threadIdx.x;
    int n = gid >> 4;
    int j = gid & 15;
    float za = fmaxf(g_AGG2[n * LATENTC + j] + __ldg(&bg2[j]), 0.f);
    out[Z_OFF + (size_t)n * 32 + j] = za;
}

// side-stream: zx half of z + g_HD (applies be1+relu to HE pre-sum)
__global__ void __launch_bounds__(128) k_node_zx(
    const float* __restrict__ be1, const float* __restrict__ We2,
    const float* __restrict__ be2, const float* __restrict__ Wd1,
    const float* __restrict__ bd1, float* __restrict__ out)
{
    __shared__ float We2s[512], Wd1s[512], be1s[32], be2s[16], bd1s[32];
    const int t = threadIdx.x;
    for (int i = t; i < 512; i += 128) { We2s[i] = We2[i]; Wd1s[i] = Wd1[i]; }
    if (t < 16) be2s[t] = be2[t];
    if (t < 32) { bd1s[t] = bd1[t]; be1s[t] = be1[t]; }
    __syncthreads();

    const int n = blockIdx.x * 128 + t;
    float he[32];
#pragma unroll
    for (int i = 0; i < 8; i++) {
        float4 v = *(const float4*)&g_HE[n * NHIDC + i * 4];
        he[i * 4 + 0] = fmaxf(v.x + be1s[i * 4 + 0], 0.f);
        he[i * 4 + 1] = fmaxf(v.y + be1s[i * 4 + 1], 0.f);
        he[i * 4 + 2] = fmaxf(v.z + be1s[i * 4 + 2], 0.f);
        he[i * 4 + 3] = fmaxf(v.w + be1s[i * 4 + 3], 0.f);
    }
    float zx[16];
#pragma unroll
    for (int j = 0; j < 16; j++) {
        float s = be2s[j];
#pragma unroll
        for (int i = 0; i < 32; i++) s += he[i] * We2s[i * 16 + j];
        zx[j] = fmaxf(s, 0.f);
    }
    float* zo = out + Z_OFF + (size_t)n * 32;
#pragma unroll
    for (int j = 0; j < 16; j++) zo[16 + j] = zx[j];
#pragma unroll
    for (int i = 0; i < 32; i++) {
        float s = bd1s[i];
#pragma unroll
        for (int j = 0; j < 16; j++) s += zx[j] * Wd1s[j * 32 + i];
        g_HD[n * NHIDC + i] = fmaxf(s, 0.f);
    }
}

__global__ void __launch_bounds__(256) k_feat(
    const float* __restrict__ Wd2, const float* __restrict__ bd2, float* __restrict__ out)
{
    __shared__ float2 hds2[16][32];
    const int t = threadIdx.x;
    const int nb = blockIdx.x * 16;
#pragma unroll
    for (int i = 0; i < 2; i++) {
        int idx = t + i * 256;
        int n = idx >> 5; int c = idx & 31;
        float v = g_HD[(nb + n) * NHIDC + c];
        hds2[n][c] = make_float2(v, v);
    }
    __syncthreads();

    const int c  = t & 127;
    const int ng = (t >> 7) * 8;
    unsigned long long accA[8], accB[8];
#pragma unroll
    for (int nn = 0; nn < 8; nn++) { accA[nn] = 0ull; accB[nn] = 0ull; }

#pragma unroll
    for (int k = 0; k < 32; k++) {
        float4 wv = __ldg((const float4*)&Wd2[k * D_FEATC + c * 4]);
        unsigned long long w01 = pack2(wv.x, wv.y);
        unsigned long long w23 = pack2(wv.z, wv.w);
#pragma unroll
        for (int nn = 0; nn < 8; nn++) {
            unsigned long long h2 = *(const unsigned long long*)&hds2[ng + nn][k];
            ffma2(accA[nn], h2, w01);
            ffma2(accB[nn], h2, w23);
        }
    }
    float4 b = __ldg((const float4*)&bd2[c * 4]);
#pragma unroll
    for (int nn = 0; nn < 8; nn++) {
        float2 vA = unpack2(accA[nn]);
        float2 vB = unpack2(accB[nn]);
        float4 o;
        o.x = fmaxf(vA.x + b.x, 0.f);
        o.y = fmaxf(vA.y + b.y, 0.f);
        o.z = fmaxf(vB.x + b.z, 0.f);
        o.w = fmaxf(vB.y + b.w, 0.f);
        *(float4*)&out[FEAT_OFF + (size_t)(nb + ng + nn) * D_FEATC + c * 4] = o;
    }
}

// ---------------- warp-MMA adjacency (compact [Hi|Lo] smem) ----------------
#define AW 72
#define ADJ_SMEM (2 * 128 * AW * 2)      // 36864 bytes

__global__ void __launch_bounds__(256) k_adj_wm(
    const float* __restrict__ zmat, float* __restrict__ out)
{
    extern __shared__ __nv_bfloat16 sm[];
    __nv_bfloat16* Asm = sm;                 // [128][AW]
    __nv_bfloat16* Bsm = sm + 128 * AW;      // [128][AW]

    const int t = threadIdx.x;
    const int wid = t >> 5;
    const int lane = t & 31;

    const int T = 64;
    const int b = blockIdx.x;
    float disc = 129.0f * 129.0f - 8.0f * (float)b;
    int it = (int)((129.0f - sqrtf(disc)) * 0.5f);
    while (it > 0 && b < it * T - (it * (it - 1)) / 2) it--;
    while (b >= (it + 1) * T - ((it + 1) * it) / 2) it++;
    const int jt = it + (b - (it * T - (it * (it - 1)) / 2));

    for (int idx = t; idx < 2048; idx += 256) {
        int half = idx >> 10;
        int rem  = idx & 1023;
        int row  = rem >> 3;
        int q    = rem & 7;
        int tl   = half ? jt : it;
        float4 v = *(const float4*)&zmat[((size_t)tl * 128 + row) * 32 + q * 4];

        __nv_bfloat16 h0 = __float2bfloat16(v.x);
        __nv_bfloat16 h1 = __float2bfloat16(v.y);
        __nv_bfloat16 h2 = __float2bfloat16(v.z);
        __nv_bfloat16 h3 = __float2bfloat16(v.w);
        __nv_bfloat16 l0 = __float2bfloat16(v.x - __bfloat162float(h0));
        __nv_bfloat16 l1 = __float2bfloat16(v.y - __bfloat162float(h1));
        __nv_bfloat16 l2 = __float2bfloat16(v.z - __bfloat162float(h2));
        __nv_bfloat16 l3 = __float2bfloat16(v.w - __bfloat162float(h3));

        __nv_bfloat162 hp0 = __nv_bfloat162(h0, h1), hp1 = __nv_bfloat162(h2, h3);
        __nv_bfloat162 lp0 = __nv_bfloat162(l0, l1), lp1 = __nv_bfloat162(l2, l3);
        uint2 hw = make_uint2(*(uint32_t*)&hp0, *(uint32_t*)&hp1);
        uint2 lw = make_uint2(*(uint32_t*)&lp0, *(uint32_t*)&lp1);

        __nv_bfloat16* base = (half ? Bsm : Asm) + row * AW + q * 4;
        *(uint2*)(base + 0)  = hw;            // Hi @ [0,32)
        *(uint2*)(base + 32) = lw;            // Lo @ [32,64)
    }
    __syncthreads();

    const int wm = wid & 3;
    const int wn = wid >> 2;
    const int rowW = wm * 32;
    const int colW = wn * 64;

    float c[2][8][4];
#pragma unroll
    for (int mi = 0; mi < 2; mi++)
#pragma unroll
        for (int ni = 0; ni < 8; ni++)
#pragma unroll
            for (int r = 0; r < 4; r++) c[mi][ni][r] = 0.f;

    const uint32_t aBase = smem_u32(Asm);
    const uint32_t bBase = smem_u32(Bsm);
    const int la_r = lane & 15;
    const int la_c = (lane >> 4) * 8;
    const int lb_r = (lane & 7) + ((lane >> 4) * 8);
    const int lb_c = ((lane >> 3) & 1) * 8;

    const int aOffs[6] = {0, 16, 0, 16, 32, 48};
    const int bOffs[6] = {0, 16, 32, 48, 0, 16};

#pragma unroll
    for (int kc = 0; kc < 6; kc++) {
        const int ka = aOffs[kc];
        const int kb = bOffs[kc];
        uint32_t a[2][4];
#pragma unroll
        for (int mi = 0; mi < 2; mi++) {
            uint32_t addr = aBase + ((rowW + mi * 16 + la_r) * AW + ka + la_c) * 2;
            ldsm_x4(a[mi][0], a[mi][1], a[mi][2], a[mi][3], addr);
        }
        uint32_t bfr[8][2];
#pragma unroll
        for (int nb2 = 0; nb2 < 4; nb2++) {
            uint32_t addr = bBase + ((colW + nb2 * 16 + lb_r) * AW + kb + lb_c) * 2;
            uint32_t t0, t1, t2, t3;
            ldsm_x4(t0, t1, t2, t3, addr);
            bfr[nb2 * 2 + 0][0] = t0; bfr[nb2 * 2 + 0][1] = t1;
            bfr[nb2 * 2 + 1][0] = t2; bfr[nb2 * 2 + 1][1] = t3;
        }
#pragma unroll
        for (int mi = 0; mi < 2; mi++)
#pragma unroll
            for (int ni = 0; ni < 8; ni++)
                mma_16816(c[mi][ni], a[mi], bfr[ni]);
    }

    const int rThr = lane >> 2;
    const int cThr = (lane & 3) * 2;
    const size_t gi0 = (size_t)it * 128;
    const size_t gj0 = (size_t)jt * 128;

#pragma unroll
    for (int mi = 0; mi < 2; mi++) {
#pragma unroll
        for (int ni = 0; ni < 8; ni++) {
            float s0 = sigf(c[mi][ni][0]);
            float s1 = sigf(c[mi][ni][1]);
            float s2 = sigf(c[mi][ni][2]);
            float s3 = sigf(c[mi][ni][3]);
            int r0 = rowW + mi * 16 + rThr;
            int cc = colW + ni * 8 + cThr;
            *(float2*)&out[(gi0 + r0)     * (size_t)N_NODESC + gj0 + cc] = make_float2(s0, s1);
            *(float2*)&out[(gi0 + r0 + 8) * (size_t)N_NODESC + gj0 + cc] = make_float2(s2, s3);
            if (it != jt) {
                out[(gj0 + cc)     * (size_t)N_NODESC + gi0 + r0]     = s0;
                out[(gj0 + cc + 1) * (size_t)N_NODESC + gi0 + r0]     = s1;
                out[(gj0 + cc)     * (size_t)N_NODESC + gi0 + r0 + 8] = s2;
                out[(gj0 + cc + 1) * (size_t)N_NODESC + gi0 + r0 + 8] = s3;
            }
        }
    }
}

// ---------------- launch ----------------
extern "C" void kernel_launch(void* const* d_in, const int* in_sizes, int n_in,
                              void* d_out, int out_size)
{
    const float* X   = (const float*)d_in[0];
    const int*   esrc= (const int*)  d_in[1];
    const int*   edst= (const int*)  d_in[2];
    const float* ew  = (const float*)d_in[3];
    const float* Wg1 = (const float*)d_in[4];
    const float* bg1 = (const float*)d_in[5];
    const float* Wg2 = (const float*)d_in[6];
    const float* bg2 = (const float*)d_in[7];
    const float* We1 = (const float*)d_in[8];
    const float* be1 = (const float*)d_in[9];
    const float* We2 = (const float*)d_in[10];
    const float* be2 = (const float*)d_in[11];
    const float* Wd1 = (const float*)d_in[12];
    const float* bd1 = (const float*)d_in[13];
    const float* Wd2 = (const float*)d_in[14];
    const float* bd2 = (const float*)d_in[15];
    float* out = (float*)d_out;

    static int initDone = 0;
    static cudaStream_t s2;
    static cudaEvent_t evFork, evZx, evJoin;
    if (!initDone) {
        cudaFuncSetAttribute(k_adj_wm, cudaFuncAttributeMaxDynamicSharedMemorySize, ADJ_SMEM);
        cudaStreamCreateWithFlags(&s2, cudaStreamNonBlocking);
        cudaEventCreateWithFlags(&evFork, cudaEventDisableTiming);
        cudaEventCreateWithFlags(&evZx,   cudaEventDisableTiming);
        cudaEventCreateWithFlags(&evJoin, cudaEventDisableTiming);
        initDone = 1;
    }

    // critical chain: zero -> fused K-split transform (atomic accum)
    k_zero     <<<896, 256>>>();
    k_transform<<<512, 256>>>(X, Wg1, We1);

    // fork side chain (needs HE pre-sums from transform)
    cudaEventRecord(evFork, 0);
    cudaStreamWaitEvent(s2, evFork, 0);
    k_node_zx <<<64, 128, 0, s2>>>(be1, We2, be2, Wd1, bd1, out);
    cudaEventRecord(evZx, s2);
    k_feat    <<<512, 256, 0, s2>>>(Wd2, bd2, out);
    cudaEventRecord(evJoin, s2);

    // graph chain
    k_agg1       <<<4096, 256>>>(esrc, edst, ew);
    k_layer2pre  <<<512, 256>>>(bg1, Wg2);
    k_agg2       <<<2048, 256>>>(esrc, edst, ew);
    k_node_za    <<<512, 256>>>(bg2, out);

    cudaStreamWaitEvent(0, evZx, 0);     // zx half of z must be written
    k_adj_wm     <<<2080, 256, ADJ_SMEM>>>(out + Z_OFF, out);

    cudaStreamWaitEvent(0, evJoin, 0);   // join feat branch
}